// round 7
// baseline (speedup 1.0000x reference)
#include <cuda_runtime.h>

// Fixed problem shape (from setup_inputs): B=16, T=1024, D=512, max_len=4096.
#define B_DIM 16
#define T_DIM 1024
#define D_DIM 512
#define MAXLEN 4096
#define D4 (D_DIM / 4)          // 128 float4 per row
#define ROWS_PB 16              // output rows per copy block

// Scratch: per-output-position source row index; -1 = masked (zero output).
__device__ int g_src[B_DIM * MAXLEN];

// ---------------------------------------------------------------------------
// Kernel 1: scan durations + scatter source indices (int32 durations, proven
// in rounds 1/2). One block per batch, 1024 threads.
// ---------------------------------------------------------------------------
__global__ void lr_scan_scatter(const int* __restrict__ dur) {
    __shared__ int warp_sums[32];
    const int b = blockIdx.x;
    const int t = threadIdx.x;

    int v = dur[b * T_DIM + t];
    if (v < 0) v = 0;

    const int lane = t & 31;
    const int w = t >> 5;

    int s = v;
    #pragma unroll
    for (int o = 1; o < 32; o <<= 1) {
        int n = __shfl_up_sync(0xFFFFFFFFu, s, o);
        if (lane >= o) s += n;
    }
    if (lane == 31) warp_sums[w] = s;
    __syncthreads();

    if (w == 0) {
        int ws = warp_sums[lane];
        #pragma unroll
        for (int o = 1; o < 32; o <<= 1) {
            int n = __shfl_up_sync(0xFFFFFFFFu, ws, o);
            if (lane >= o) ws += n;
        }
        warp_sums[lane] = ws;
    }
    __syncthreads();

    const int incl = s + ((w > 0) ? warp_sums[w - 1] : 0);  // csum[t]
    const int excl = incl - v;                              // csum[t-1]

    int* __restrict__ src = g_src + b * MAXLEN;
    #pragma unroll
    for (int j = 0; j < MAXLEN / T_DIM; j++)
        src[t + j * T_DIM] = -1;
    __syncthreads();

    for (int p = excl; p < incl; p++)      // durations < 8: <= 7 stores
        src[p] = t;
}

// ---------------------------------------------------------------------------
// Kernel 2: smem-staged copy. Block = 16 output rows of one batch.
//   1. warp 0: read the 16 source indices (monotonic, -1 = masked),
//      dedupe via ballot/popc -> slot table + unique source list
//   2. block loads each UNIQUE x row ONCE (gmem -> smem, 2KB/row)
//      => L2 read traffic drops ~3.5x vs reading per output row
//   3. each warp stores 2 output rows from smem (conflict-free LDS.128)
// ---------------------------------------------------------------------------
__global__ void __launch_bounds__(256) lr_copy(
    const float4* __restrict__ x, float4* __restrict__ out)
{
    __shared__ float4 s_data[ROWS_PB][D4];   // 32 KB
    __shared__ int s_slot[ROWS_PB];
    __shared__ int s_usrc[ROWS_PB];
    __shared__ int s_nu;

    const int tid  = threadIdx.x;
    const int lane = tid & 31;
    const int w    = tid >> 5;
    const int b    = blockIdx.x >> 8;                 // 256 chunks per batch
    const int base = (blockIdx.x & 255) * ROWS_PB;

    // ---- dedupe source indices (warp 0) ----
    if (w == 0) {
        int v = (lane < ROWS_PB) ? __ldg(&g_src[b * MAXLEN + base + lane]) : -1;
        int pv = __shfl_up_sync(0xFFFFFFFFu, v, 1);
        const bool valid = (lane < ROWS_PB) && (v >= 0);
        const bool isnew = valid && (lane == 0 || v != pv);
        const unsigned m = __ballot_sync(0xFFFFFFFFu, isnew);
        const int myslot = valid ? (__popc(m & ((2u << lane) - 1)) - 1) : -1;
        if (lane < ROWS_PB) s_slot[lane] = myslot;
        if (isnew) s_usrc[myslot] = v;
        if (lane == 0) s_nu = __popc(m);
    }
    __syncthreads();
    const int nu = s_nu;

    // ---- load unique source rows into smem (warp w -> slots w, w+8) ----
    const float4* __restrict__ xb = x + (size_t)b * T_DIM * D4;
    #pragma unroll
    for (int u = w; u < ROWS_PB; u += 8) {
        if (u < nu) {
            const float4* __restrict__ xr = xb + (size_t)s_usrc[u] * D4;
            #pragma unroll
            for (int j = 0; j < 4; j++)
                s_data[u][lane + j * 32] = __ldg(&xr[lane + j * 32]);
        }
    }
    __syncthreads();

    // ---- store: warp w writes output rows w*2, w*2+1 ----
    float4* __restrict__ o = out + (size_t)(b * MAXLEN + base + w * 2) * D4;
    const float4 z = make_float4(0.f, 0.f, 0.f, 0.f);
    #pragma unroll
    for (int k = 0; k < 2; k++) {
        const int sl = s_slot[w * 2 + k];            // warp-uniform
        float4* __restrict__ orow = o + (size_t)k * D4;
        if (sl >= 0) {
            #pragma unroll
            for (int j = 0; j < 4; j++)
                __stcs(&orow[lane + j * 32], s_data[sl][lane + j * 32]);
        } else {
            #pragma unroll
            for (int j = 0; j < 4; j++)
                __stcs(&orow[lane + j * 32], z);
        }
    }
}

// ---------------------------------------------------------------------------
extern "C" void kernel_launch(void* const* d_in, const int* in_sizes, int n_in,
                              void* d_out, int out_size) {
    const float4* x   = (const float4*)d_in[0];
    const int*    dur = (const int*)d_in[1];
    float4*       out = (float4*)d_out;
    (void)in_sizes; (void)n_in; (void)out_size;

    lr_scan_scatter<<<B_DIM, T_DIM>>>(dur);

    // one block per 16 output rows: 16 * 256 = 4096 blocks
    lr_copy<<<B_DIM * (MAXLEN / ROWS_PB), 256>>>(x, out);
}